// round 5
// baseline (speedup 1.0000x reference)
#include <cuda_runtime.h>
#include <cuda_bf16.h>
#include <cstdint>

namespace {
constexpr int B_ = 32, S_ = 500, C_ = 1024, H_ = 16, D_ = 64;
constexpr int BH_ = B_ * H_;   // 512
constexpr int M_  = B_ * S_;   // 16000

// GEMM: CTA tile 128x256, BK=64. Stage: [Ahi 16K][Alo 16K][Bhi 32K][Blo 32K]
constexpr int OFF_AHI = 0;
constexpr int OFF_ALO = 16384;
constexpr int OFF_BHI = 32768;
constexpr int OFF_BLO = 65536;
constexpr int STAGE   = 98304;       // 96KB
constexpr int GSMEM   = STAGE * 2;   // 192KB

// Attention: q-tile 128 rows, kt tiles 64. Q hi/lo 16K each; KV stage 32K x2
constexpr int AQHI = 0;
constexpr int AQLO = 16384;
constexpr int AKV0 = 32768;
constexpr int AKHI = 0, AKLO = 8192, AVHI = 16384, AVLO = 24576;
constexpr int AKV_STRIDE = 32768;
constexpr int ASMEM = AKV0 + 2 * AKV_STRIDE;  // 96KB
}

// Scratch (__device__ globals: allocation-free rule)
__device__ __align__(128) __nv_bfloat16 g_qhi[(size_t)BH_ * S_ * D_];
__device__ __align__(128) __nv_bfloat16 g_qlo[(size_t)BH_ * S_ * D_];
__device__ __align__(128) __nv_bfloat16 g_khi[(size_t)BH_ * S_ * D_];
__device__ __align__(128) __nv_bfloat16 g_klo[(size_t)BH_ * S_ * D_];
__device__ __align__(128) __nv_bfloat16 g_vhi[(size_t)BH_ * S_ * D_];
__device__ __align__(128) __nv_bfloat16 g_vlo[(size_t)BH_ * S_ * D_];
__device__ __align__(128) __nv_bfloat16 g_xhi[(size_t)M_ * C_];
__device__ __align__(128) __nv_bfloat16 g_xlo[(size_t)M_ * C_];
__device__ __align__(128) __nv_bfloat16 g_yhi[(size_t)M_ * C_];
__device__ __align__(128) __nv_bfloat16 g_ylo[(size_t)M_ * C_];
__device__ __align__(128) __nv_bfloat16 g_whi[4u * 1024u * 1024u];  // [z][n][k]
__device__ __align__(128) __nv_bfloat16 g_wlo[4u * 1024u * 1024u];

// ---------------------------------------------------------------------------
// helpers
// ---------------------------------------------------------------------------
static __device__ __forceinline__ uint32_t s2u(const void* p) {
    uint32_t a;
    asm("{ .reg .u64 t; cvta.to.shared.u64 t, %1; cvt.u32.u64 %0, t; }"
        : "=r"(a) : "l"(p));
    return a;
}
static __device__ __forceinline__ uint32_t swz(uint32_t o) {
    return o ^ ((o >> 3) & 0x70u);
}
static __device__ __forceinline__ void cpa16(uint32_t s, const void* g) {
    asm volatile("cp.async.cg.shared.global [%0], [%1], 16;" :: "r"(s), "l"(g));
}
static __device__ __forceinline__ void cpa16z(uint32_t s, const void* g, uint32_t sz) {
    asm volatile("cp.async.cg.shared.global [%0], [%1], 16, %2;"
                 :: "r"(s), "l"(g), "r"(sz));
}
static __device__ __forceinline__ uint32_t packbf2(float a, float b) {
    __nv_bfloat162 h = __floats2bfloat162_rn(a, b);
    return *(uint32_t*)&h;
}

#define LDSM4(r0, r1, r2, r3, a) \
    asm volatile("ldmatrix.sync.aligned.m8n8.x4.shared.b16 {%0,%1,%2,%3}, [%4];" \
                 : "=r"(r0), "=r"(r1), "=r"(r2), "=r"(r3) : "r"(a))
#define LDSM4T(r0, r1, r2, r3, a) \
    asm volatile("ldmatrix.sync.aligned.m8n8.x4.trans.shared.b16 {%0,%1,%2,%3}, [%4];" \
                 : "=r"(r0), "=r"(r1), "=r"(r2), "=r"(r3) : "r"(a))

#define MMA_BF16(d, a, b0, b1) \
    asm volatile( \
        "mma.sync.aligned.m16n8k16.row.col.f32.bf16.bf16.f32 " \
        "{%0,%1,%2,%3}, {%4,%5,%6,%7}, {%8,%9}, {%0,%1,%2,%3};" \
        : "+f"((d)[0]), "+f"((d)[1]), "+f"((d)[2]), "+f"((d)[3]) \
        : "r"((a)[0]), "r"((a)[1]), "r"((a)[2]), "r"((a)[3]), \
          "r"(b0), "r"(b1))

// ---------------------------------------------------------------------------
// GEMM core: C[128x256] = A[128x1024] * B^T (B stored [n][k]), bf16x3 splits
// 512 threads, 16 warps (4m x 4n), warp tile 32x64, BK=64, 2-stage pipeline
// ---------------------------------------------------------------------------
static __device__ __forceinline__ void load_stage(
    uint32_t sb, int buf,
    const __nv_bfloat16* __restrict__ Ahi, const __nv_bfloat16* __restrict__ Alo,
    const __nv_bfloat16* __restrict__ Bhi, const __nv_bfloat16* __restrict__ Blo,
    int m0, int n0, int k0, int tid)
{
    const uint32_t base = sb + buf * STAGE;
    // A: 128 rows x 128B per split; thread -> (row, 32B quarter)
    const int ra = tid >> 2, qa = tid & 3;
    const size_t ga = (size_t)(m0 + ra) * C_ + k0 + qa * 16;
#pragma unroll
    for (int i = 0; i < 2; i++) {
        uint32_t so = swz((uint32_t)(ra * 128 + qa * 32 + i * 16));
        cpa16(base + OFF_AHI + so, Ahi + ga + i * 8);
        cpa16(base + OFF_ALO + so, Alo + ga + i * 8);
    }
    // B: 256 rows x 128B per split; thread -> (row, 64B half)
    const int rb = tid >> 1, hb = tid & 1;
    const size_t gb = (size_t)(n0 + rb) * C_ + k0 + hb * 32;
#pragma unroll
    for (int i = 0; i < 4; i++) {
        uint32_t so = swz((uint32_t)(rb * 128 + hb * 64 + i * 16));
        cpa16(base + OFF_BHI + so, Bhi + gb + i * 8);
        cpa16(base + OFF_BLO + so, Blo + gb + i * 8);
    }
}

static __device__ __forceinline__ void compute_stage(
    uint32_t base, int wm, int wn, int lane, float acc[2][8][4])
{
    const uint32_t arow  = wm * 32 + (lane & 15);
    const uint32_t acolk = (lane & 16) ? 16u : 0u;
    const uint32_t brow  = wn * 64 + (lane & 7) + ((lane & 16) ? 8u : 0u);
    const uint32_t bcolk = (lane & 8) ? 16u : 0u;

#pragma unroll
    for (int kk = 0; kk < 4; kk++) {
        const uint32_t ac = kk * 32 + acolk;
        const uint32_t bc = kk * 32 + bcolk;
        uint32_t ah[2][4], al[2][4];
#pragma unroll
        for (int mt = 0; mt < 2; mt++) {
            uint32_t off = swz((arow + mt * 16) * 128 + ac);
            LDSM4(ah[mt][0], ah[mt][1], ah[mt][2], ah[mt][3], base + OFF_AHI + off);
            LDSM4(al[mt][0], al[mt][1], al[mt][2], al[mt][3], base + OFF_ALO + off);
        }
#pragma unroll
        for (int ng = 0; ng < 4; ng++) {
            uint32_t off = swz((brow + ng * 16) * 128 + bc);
            uint32_t bh[4], bl[4];
            LDSM4(bh[0], bh[1], bh[2], bh[3], base + OFF_BHI + off);
            LDSM4(bl[0], bl[1], bl[2], bl[3], base + OFF_BLO + off);
#pragma unroll
            for (int mt = 0; mt < 2; mt++) {
                MMA_BF16(acc[mt][2 * ng],     ah[mt], bh[0], bh[1]);
                MMA_BF16(acc[mt][2 * ng],     ah[mt], bl[0], bl[1]);
                MMA_BF16(acc[mt][2 * ng],     al[mt], bh[0], bh[1]);
                MMA_BF16(acc[mt][2 * ng + 1], ah[mt], bh[2], bh[3]);
                MMA_BF16(acc[mt][2 * ng + 1], ah[mt], bl[2], bl[3]);
                MMA_BF16(acc[mt][2 * ng + 1], al[mt], bh[2], bh[3]);
            }
        }
    }
}

static __device__ __forceinline__ void gemm_core(
    uint32_t sb,
    const __nv_bfloat16* Ahi, const __nv_bfloat16* Alo,
    const __nv_bfloat16* Bhi, const __nv_bfloat16* Blo,
    int m0, int n0, float acc[2][8][4])
{
    const int tid = threadIdx.x;
    const int wid = tid >> 5, lane = tid & 31;
    const int wm = wid >> 2, wn = wid & 3;

#pragma unroll
    for (int mt = 0; mt < 2; mt++)
#pragma unroll
        for (int nf = 0; nf < 8; nf++)
#pragma unroll
            for (int j = 0; j < 4; j++) acc[mt][nf][j] = 0.f;

    load_stage(sb, 0, Ahi, Alo, Bhi, Blo, m0, n0, 0, tid);
    asm volatile("cp.async.commit_group;" ::: "memory");

    for (int s = 0; s < 16; s++) {
        asm volatile("cp.async.wait_group 0;" ::: "memory");
        __syncthreads();
        if (s + 1 < 16) {
            load_stage(sb, (s + 1) & 1, Ahi, Alo, Bhi, Blo, m0, n0,
                       (s + 1) * 64, tid);
            asm volatile("cp.async.commit_group;" ::: "memory");
        }
        compute_stage(sb + (s & 1) * STAGE, wm, wn, lane, acc);
    }
}

// ---------------------------------------------------------------------------
// QKV projection: epilogue emits bf16 hi/lo into [B,H,S,D]; Q scaled by 1/8
// ---------------------------------------------------------------------------
__global__ __launch_bounds__(512, 1) void qkv_mma(
    const float* __restrict__ bq, const float* __restrict__ bk,
    const float* __restrict__ bv)
{
    extern __shared__ __align__(1024) char dsm[];
    const uint32_t sb = s2u(dsm);
    const int tid = threadIdx.x, wid = tid >> 5, lane = tid & 31;
    const int wm = wid >> 2, wn = wid & 3;

    const int which = blockIdx.z;
    const __nv_bfloat16* Bhi = g_whi + ((size_t)which << 20);
    const __nv_bfloat16* Blo = g_wlo + ((size_t)which << 20);
    const float* bias = (which == 0) ? bq : (which == 1) ? bk : bv;
    __nv_bfloat16* dhi = (which == 0) ? g_qhi : (which == 1) ? g_khi : g_vhi;
    __nv_bfloat16* dlo = (which == 0) ? g_qlo : (which == 1) ? g_klo : g_vlo;
    const float scale = (which == 0) ? 0.125f : 1.0f;

    const int m0 = blockIdx.y * 128, n0 = blockIdx.x * 256;
    float acc[2][8][4];
    gemm_core(sb, g_xhi, g_xlo, Bhi, Blo, m0, n0, acc);

    const int qr = lane >> 2, qc = (lane & 3) * 2;
#pragma unroll
    for (int mt = 0; mt < 2; mt++) {
        const int mr0 = m0 + wm * 32 + mt * 16 + qr;
        const int mr1 = mr0 + 8;
        const int b0 = mr0 / S_, s0 = mr0 - b0 * S_;
        const int b1 = mr1 / S_, s1 = mr1 - b1 * S_;
#pragma unroll
        for (int nf = 0; nf < 8; nf++) {
            const int c = n0 + wn * 64 + nf * 8 + qc;
            const int h = c >> 6, dc = c & 63;
            const float bx = bias[c], by = bias[c + 1];
            float v0 = (acc[mt][nf][0] + bx) * scale;
            float v1 = (acc[mt][nf][1] + by) * scale;
            float v2 = (acc[mt][nf][2] + bx) * scale;
            float v3 = (acc[mt][nf][3] + by) * scale;
            size_t i0 = ((size_t)(b0 * H_ + h) * S_ + s0) * D_ + dc;
            size_t i1 = ((size_t)(b1 * H_ + h) * S_ + s1) * D_ + dc;
            __nv_bfloat162 h0 = __floats2bfloat162_rn(v0, v1);
            __nv_bfloat162 h1 = __floats2bfloat162_rn(v2, v3);
            __nv_bfloat162 l0 = __floats2bfloat162_rn(v0 - __low2float(h0),
                                                      v1 - __high2float(h0));
            __nv_bfloat162 l1 = __floats2bfloat162_rn(v2 - __low2float(h1),
                                                      v3 - __high2float(h1));
            *(__nv_bfloat162*)(dhi + i0) = h0;
            *(__nv_bfloat162*)(dhi + i1) = h1;
            *(__nv_bfloat162*)(dlo + i0) = l0;
            *(__nv_bfloat162*)(dlo + i1) = l1;
        }
    }
}

// ---------------------------------------------------------------------------
// Output projection: reads y splits, writes d_out row-major
// ---------------------------------------------------------------------------
__global__ __launch_bounds__(512, 1) void proj_mma(
    const float* __restrict__ bp, float* __restrict__ out)
{
    extern __shared__ __align__(1024) char dsm[];
    const uint32_t sb = s2u(dsm);
    const int tid = threadIdx.x, wid = tid >> 5, lane = tid & 31;
    const int wm = wid >> 2, wn = wid & 3;

    const __nv_bfloat16* Bhi = g_whi + ((size_t)3 << 20);
    const __nv_bfloat16* Blo = g_wlo + ((size_t)3 << 20);

    const int m0 = blockIdx.y * 128, n0 = blockIdx.x * 256;
    float acc[2][8][4];
    gemm_core(sb, g_yhi, g_ylo, Bhi, Blo, m0, n0, acc);

    const int qr = lane >> 2, qc = (lane & 3) * 2;
#pragma unroll
    for (int mt = 0; mt < 2; mt++) {
        const int mr0 = m0 + wm * 32 + mt * 16 + qr;
#pragma unroll
        for (int nf = 0; nf < 8; nf++) {
            const int c = n0 + wn * 64 + nf * 8 + qc;
            const float bx = bp[c], by = bp[c + 1];
            *(float2*)(out + (size_t)mr0 * C_ + c) =
                make_float2(acc[mt][nf][0] + bx, acc[mt][nf][1] + by);
            *(float2*)(out + (size_t)(mr0 + 8) * C_ + c) =
                make_float2(acc[mt][nf][2] + bx, acc[mt][nf][3] + by);
        }
    }
}

// ---------------------------------------------------------------------------
// Pre-pass: split x / transpose+split weights
// ---------------------------------------------------------------------------
__global__ void split_x_kernel(const float* __restrict__ x)
{
    const size_t i = ((size_t)blockIdx.x * 256 + threadIdx.x) * 4;
    float4 v = *(const float4*)(x + i);
    __nv_bfloat162 h01 = __floats2bfloat162_rn(v.x, v.y);
    __nv_bfloat162 h23 = __floats2bfloat162_rn(v.z, v.w);
    __nv_bfloat162 l01 = __floats2bfloat162_rn(v.x - __low2float(h01),
                                               v.y - __high2float(h01));
    __nv_bfloat162 l23 = __floats2bfloat162_rn(v.z - __low2float(h23),
                                               v.w - __high2float(h23));
    *(__nv_bfloat162*)(g_xhi + i)     = h01;
    *(__nv_bfloat162*)(g_xhi + i + 2) = h23;
    *(__nv_bfloat162*)(g_xlo + i)     = l01;
    *(__nv_bfloat162*)(g_xlo + i + 2) = l23;
}

__global__ void wsplit_kernel(
    const float* __restrict__ Wq, const float* __restrict__ Wk,
    const float* __restrict__ Wv, const float* __restrict__ Wp)
{
    __shared__ float t[32][33];
    const int z = blockIdx.z;
    const float* src = (z == 0) ? Wq : (z == 1) ? Wk : (z == 2) ? Wv : Wp;
    const size_t zoff = (size_t)z << 20;
    const int x0 = blockIdx.x * 32, y0 = blockIdx.y * 32;
    const int tx = threadIdx.x, ty = threadIdx.y;
#pragma unroll
    for (int i = 0; i < 32; i += 8)
        t[ty + i][tx] = src[(size_t)(y0 + ty + i) * 1024 + x0 + tx];
    __syncthreads();
#pragma unroll
    for (int i = 0; i < 32; i += 8) {
        float v = t[tx][ty + i];
        __nv_bfloat16 h = __float2bfloat16(v);
        size_t o = zoff + (size_t)(x0 + ty + i) * 1024 + (y0 + tx);
        g_whi[o] = h;
        g_wlo[o] = __float2bfloat16(v - __bfloat162float(h));
    }
}

// ---------------------------------------------------------------------------
// Flash attention on tensor cores: 8 warps, 128 q-rows, bf16x3 both GEMMs
// ---------------------------------------------------------------------------
static __device__ __forceinline__ void attn_load_kv(
    uint32_t sb, int buf, size_t boff, int kt, int tid)
{
    const int r = tid >> 2;             // 0..63
    const int cb = (tid & 3) * 2;       // chunk base 0..6
    const int kpos = kt * 64 + r;
    const uint32_t sz = (kpos < S_) ? 16u : 0u;
    const int kc = (kpos < S_) ? kpos : (S_ - 1);
    const uint32_t base = sb + AKV0 + buf * AKV_STRIDE;
    const size_t g = boff + (size_t)kc * D_;
#pragma unroll
    for (int i = 0; i < 2; i++) {
        const int chunk = cb + i;
        const uint32_t sw = swz((uint32_t)(r * 128 + chunk * 16));
        cpa16z(base + AKHI + sw, g_khi + g + chunk * 8, sz);
        cpa16z(base + AKLO + sw, g_klo + g + chunk * 8, sz);
        cpa16z(base + AVHI + sw, g_vhi + g + chunk * 8, sz);
        cpa16z(base + AVLO + sw, g_vlo + g + chunk * 8, sz);
    }
}

__global__ __launch_bounds__(256, 2) void attn_mma()
{
    extern __shared__ __align__(1024) char asm_[];
    const uint32_t sb = s2u(asm_);
    const int tid = threadIdx.x, wid = tid >> 5, lane = tid & 31;
    const int qt = blockIdx.x, bh = blockIdx.y;
    const size_t boff = (size_t)bh * (S_ * D_);
    const int ktmax = min(2 * qt + 1, (S_ + 63) / 64 - 1);

    // ---- load Q tile (128 rows, hi/lo) into smem, zero-padded ----
    {
        const int r = tid >> 1;          // 0..127
        const int cb = (tid & 1) * 4;    // chunks 0-3 / 4-7
        const int qpos = qt * 128 + r;
        const bool ok = qpos < S_;
        const size_t g = boff + (size_t)(ok ? qpos : 0) * D_;
#pragma unroll
        for (int i = 0; i < 4; i++) {
            const int chunk = cb + i;
            const uint32_t sw = swz((uint32_t)(r * 128 + chunk * 16));
            float4 vh = make_float4(0, 0, 0, 0), vl = vh;
            if (ok) {
                vh = *(const float4*)(g_qhi + g + chunk * 8);
                vl = *(const float4*)(g_qlo + g + chunk * 8);
            }
            *(float4*)(asm_ + AQHI + sw) = vh;
            *(float4*)(asm_ + AQLO + sw) = vl;
        }
    }
    attn_load_kv(sb, 0, boff, 0, tid);
    asm volatile("cp.async.commit_group;" ::: "memory");
    __syncthreads();

    // ---- Q fragments (register-resident across kt loop) ----
    uint32_t qfh[4][4], qfl[4][4];
    {
        const uint32_t arow = wid * 16 + (lane & 15);
        const uint32_t ack  = (lane & 16) ? 16u : 0u;
#pragma unroll
        for (int kk = 0; kk < 4; kk++) {
            uint32_t off = swz(arow * 128 + kk * 32 + ack);
            LDSM4(qfh[kk][0], qfh[kk][1], qfh[kk][2], qfh[kk][3], sb + AQHI + off);
            LDSM4(qfl[kk][0], qfl[kk][1], qfl[kk][2], qfl[kk][3], sb + AQLO + off);
        }
    }

    float o[8][4];
#pragma unroll
    for (int dn = 0; dn < 8; dn++)
#pragma unroll
        for (int j = 0; j < 4; j++) o[dn][j] = 0.f;
    float m0v = -1e30f, m1v = -1e30f, l0v = 0.f, l1v = 0.f;

    const int row0 = qt * 128 + wid * 16 + (lane >> 2);
    const int row1 = row0 + 8;

    const uint32_t brow = (lane & 7) + ((lane & 16) ? 8u : 0u);
    const uint32_t bck  = (lane & 8) ? 16u : 0u;
    const uint32_t vrow = (lane & 7) + ((lane & 8) ? 8u : 0u);
    const uint32_t vck  = (lane & 16) ? 16u : 0u;

    for (int kt = 0; kt <= ktmax; kt++) {
        const int buf = kt & 1;
        asm volatile("cp.async.wait_group 0;" ::: "memory");
        __syncthreads();
        if (kt < ktmax) {
            attn_load_kv(sb, buf ^ 1, boff, kt + 1, tid);
            asm volatile("cp.async.commit_group;" ::: "memory");
        }

        const uint32_t kvb = sb + AKV0 + buf * AKV_STRIDE;

        // ---- S = Q @ K^T (bf16x3) ----
        float sc[8][4];
#pragma unroll
        for (int j = 0; j < 8; j++)
#pragma unroll
            for (int q = 0; q < 4; q++) sc[j][q] = 0.f;

#pragma unroll
        for (int kk = 0; kk < 4; kk++) {
#pragma unroll
            for (int j2 = 0; j2 < 4; j2++) {
                uint32_t off = swz((j2 * 16 + brow) * 128 + kk * 32 + bck);
                uint32_t kh[4], kl[4];
                LDSM4(kh[0], kh[1], kh[2], kh[3], kvb + AKHI + off);
                LDSM4(kl[0], kl[1], kl[2], kl[3], kvb + AKLO + off);
                MMA_BF16(sc[2 * j2],     qfh[kk], kh[0], kh[1]);
                MMA_BF16(sc[2 * j2],     qfh[kk], kl[0], kl[1]);
                MMA_BF16(sc[2 * j2],     qfl[kk], kh[0], kh[1]);
                MMA_BF16(sc[2 * j2 + 1], qfh[kk], kh[2], kh[3]);
                MMA_BF16(sc[2 * j2 + 1], qfh[kk], kl[2], kl[3]);
                MMA_BF16(sc[2 * j2 + 1], qfl[kk], kh[2], kh[3]);
            }
        }

        // ---- mask (scale already folded into Q) ----
        if ((kt >= 2 * qt) || ((kt + 1) * 64 > S_)) {
            const int cb = kt * 64 + (lane & 3) * 2;
#pragma unroll
            for (int j = 0; j < 8; j++) {
                const int c0 = cb + j * 8, c1 = c0 + 1;
                if (c0 > row0 || c0 >= S_) sc[j][0] = -1e30f;
                if (c1 > row0 || c1 >= S_) sc[j][1] = -1e30f;
                if (c0 > row1 || c0 >= S_) sc[j][2] = -1e30f;
                if (c1 > row1 || c1 >= S_) sc[j][3] = -1e30f;
            }
        }

        // ---- online softmax ----
        float mt0 = -1e30f, mt1 = -1e30f;
#pragma unroll
        for (int j = 0; j < 8; j++) {
            mt0 = fmaxf(mt0, fmaxf(sc[j][0], sc[j][1]));
            mt1 = fmaxf(mt1, fmaxf(sc[j][2], sc[j][3]));
        }
        mt0 = fmaxf(mt0, __shfl_xor_sync(0xffffffffu, mt0, 1));
        mt0 = fmaxf(mt0, __shfl_xor_sync(0xffffffffu, mt0, 2));
        mt1 = fmaxf(mt1, __shfl_xor_sync(0xffffffffu, mt1, 1));
        mt1 = fmaxf(mt1, __shfl_xor_sync(0xffffffffu, mt1, 2));
        const float mn0 = fmaxf(m0v, mt0), mn1 = fmaxf(m1v, mt1);
        const float cr0 = __expf(m0v - mn0), cr1 = __expf(m1v - mn1);
        m0v = mn0; m1v = mn1;

        uint32_t ph[8][2], pl[8][2];
        float rs0 = 0.f, rs1 = 0.f;
#pragma unroll
        for (int j = 0; j < 8; j++) {
            float p0 = __expf(sc[j][0] - mn0);
            float p1 = __expf(sc[j][1] - mn0);
            float p2 = __expf(sc[j][2] - mn1);
            float p3 = __expf(sc[j][3] - mn1);
            rs0 += p0 + p1; rs1 += p2 + p3;
            __nv_bfloat162 h0 = __floats2bfloat162_rn(p0, p1);
            __nv_bfloat162 h1 = __floats2bfloat162_rn(p2, p3);
            ph[j][0] = *(uint32_t*)&h0;
            ph[j][1] = *(uint32_t*)&h1;
            pl[j][0] = packbf2(p0 - __low2float(h0), p1 - __high2float(h0));
            pl[j][1] = packbf2(p2 - __low2float(h1), p3 - __high2float(h1));
        }
        rs0 += __shfl_xor_sync(0xffffffffu, rs0, 1);
        rs0 += __shfl_xor_sync(0xffffffffu, rs0, 2);
        rs1 += __shfl_xor_sync(0xffffffffu, rs1, 1);
        rs1 += __shfl_xor_sync(0xffffffffu, rs1, 2);
        l0v = l0v * cr0 + rs0;
        l1v = l1v * cr1 + rs1;
#pragma unroll
        for (int dn = 0; dn < 8; dn++) {
            o[dn][0] *= cr0; o[dn][1] *= cr0;
            o[dn][2] *= cr1; o[dn][3] *= cr1;
        }

        // ---- O += P @ V (bf16x3), V via ldmatrix.trans ----
#pragma unroll
        for (int kk = 0; kk < 4; kk++) {
            uint32_t ah[4] = {ph[2 * kk][0], ph[2 * kk][1],
                              ph[2 * kk + 1][0], ph[2 * kk + 1][1]};
            uint32_t al[4] = {pl[2 * kk][0], pl[2 * kk][1],
                              pl[2 * kk + 1][0], pl[2 * kk + 1][1]};
#pragma unroll
            for (int dj2 = 0; dj2 < 4; dj2++) {
                uint32_t off = swz((kk * 16 + vrow) * 128 + dj2 * 32 + vck);
                uint32_t vh[4], vl[4];
                LDSM4T(vh[0], vh[1], vh[2], vh[3], kvb + AVHI + off);
                LDSM4T(vl[0], vl[1], vl[2], vl[3], kvb + AVLO + off);
                MMA_BF16(o[2 * dj2],     ah, vh[0], vh[1]);
                MMA_BF16(o[2 * dj2],     ah, vl[0], vl[1]);
                MMA_BF16(o[2 * dj2],     al, vh[0], vh[1]);
                MMA_BF16(o[2 * dj2 + 1], ah, vh[2], vh[3]);
                MMA_BF16(o[2 * dj2 + 1], ah, vl[2], vl[3]);
                MMA_BF16(o[2 * dj2 + 1], al, vh[2], vh[3]);
            }
        }
        __syncthreads();  // all warps done with buf before next load overwrites
    }

    // ---- epilogue: normalize, split to bf16 hi/lo, write y [M][C] ----
    const int h = bh & (H_ - 1);
    const int b = bh >> 4;
    const float inv0 = 1.f / l0v, inv1 = 1.f / l1v;
    const int dc = (lane & 3) * 2;
#pragma unroll
    for (int dn = 0; dn < 8; dn++) {
        const int d = h * D_ + dn * 8 + dc;
        if (row0 < S_) {
            float v0 = o[dn][0] * inv0, v1 = o[dn][1] * inv0;
            __nv_bfloat162 hh = __floats2bfloat162_rn(v0, v1);
            __nv_bfloat162 ll = __floats2bfloat162_rn(v0 - __low2float(hh),
                                                      v1 - __high2float(hh));
            size_t i0 = (size_t)(b * S_ + row0) * C_ + d;
            *(__nv_bfloat162*)(g_yhi + i0) = hh;
            *(__nv_bfloat162*)(g_ylo + i0) = ll;
        }
        if (row1 < S_) {
            float v2 = o[dn][2] * inv1, v3 = o[dn][3] * inv1;
            __nv_bfloat162 hh = __floats2bfloat162_rn(v2, v3);
            __nv_bfloat162 ll = __floats2bfloat162_rn(v2 - __low2float(hh),
                                                      v3 - __high2float(hh));
            size_t i1 = (size_t)(b * S_ + row1) * C_ + d;
            *(__nv_bfloat162*)(g_yhi + i1) = hh;
            *(__nv_bfloat162*)(g_ylo + i1) = ll;
        }
    }
}

// ---------------------------------------------------------------------------
extern "C" void kernel_launch(void* const* d_in, const int* in_sizes, int n_in,
                              void* d_out, int out_size)
{
    const float* x  = (const float*)d_in[0];
    const float* Wq = (const float*)d_in[1];
    const float* bq = (const float*)d_in[2];
    const float* Wk = (const float*)d_in[3];
    const float* bk = (const float*)d_in[4];
    const float* Wv = (const float*)d_in[5];
    const float* bv = (const float*)d_in[6];
    const float* Wp = (const float*)d_in[7];
    const float* bp = (const float*)d_in[8];
    float* out = (float*)d_out;

    cudaFuncSetAttribute(qkv_mma, cudaFuncAttributeMaxDynamicSharedMemorySize, GSMEM);
    cudaFuncSetAttribute(proj_mma, cudaFuncAttributeMaxDynamicSharedMemorySize, GSMEM);
    cudaFuncSetAttribute(attn_mma, cudaFuncAttributeMaxDynamicSharedMemorySize, ASMEM);

    split_x_kernel<<<M_ * C_ / 1024, 256>>>(x);
    wsplit_kernel<<<dim3(32, 32, 4), dim3(32, 8)>>>(Wq, Wk, Wv, Wp);
    qkv_mma<<<dim3(4, 125, 3), 512, GSMEM>>>(bq, bk, bv);
    attn_mma<<<dim3(4, BH_), 256, ASMEM>>>();
    proj_mma<<<dim3(4, 125), 512, GSMEM>>>(bp, out);
}